// round 13
// baseline (speedup 1.0000x reference)
#include <cuda_runtime.h>
#include <cuda_fp16.h>
#include <cstdint>

#define BATCH 32
#define DIM   128
#define TLEN  4096
#define SZ    512

// ---- smem byte map (per CTA, 23.8 KB) ----
#define SM_M2    0        // 512 floats  -> 2048
#define SM_PSUM  2048     // 8*32 floats -> 3072
#define SM_CINV  3072     // 32 floats   -> 3200
#define SM_A     3328     // [2 comp][128 k][40 halfs=80B]; hi @0, lo @+10240 -> 20480 B
#define SM_TOTAL 23808

// fragment-packed B image, L2-resident (256 KB):
// block index = ((kc*2 + comp)*2 + ks)*32 + jglob   (jglob = s>>4), block = 512 B
// lane L, reg m (0..3), half h: element (s = 16*jglob + 8*(m>>1) + (L>>2),
//                                k = kc*32 + ks*16 + 8*(m&1) + 2*(L&3) + h)
// byte offset in block = L*16 + m*4 + h*2
__device__ __align__(128) unsigned char gUimgB[262144];
__device__ float g_m2[SZ];

__device__ __forceinline__ uint32_t smem_u32(const void* p) {
    uint32_t a;
    asm("{ .reg .u64 t; cvta.to.shared.u64 t, %1; cvt.u32.u64 %0, t; }" : "=r"(a) : "l"(p));
    return a;
}
__device__ __forceinline__ void ldsm4t(uint32_t* r, uint32_t a) {
    asm volatile("ldmatrix.sync.aligned.m8n8.x4.trans.shared.b16 {%0,%1,%2,%3}, [%4];"
                 : "=r"(r[0]),"=r"(r[1]),"=r"(r[2]),"=r"(r[3]) : "r"(a));
}
__device__ __forceinline__ void mma16816(float* d, const uint32_t* a, const uint32_t* b) {
    asm volatile("mma.sync.aligned.m16n8k16.row.col.f32.f16.f16.f32 "
                 "{%0,%1,%2,%3}, {%4,%5,%6,%7}, {%8,%9}, {%0,%1,%2,%3};"
                 : "+f"(d[0]),"+f"(d[1]),"+f"(d[2]),"+f"(d[3])
                 : "r"(a[0]),"r"(a[1]),"r"(a[2]),"r"(a[3]), "r"(b[0]),"r"(b[1]));
}

// ---- merged prep: fragment-packed hi/lo image + m2; 512 blocks (one s) x 128 thr (one k) ----
__global__ void prep_kernel(const float* __restrict__ units) {
    const int s = blockIdx.x, k = threadIdx.x;
    const int lane = k & 31;
    float x = units[k * SZ + s];
    __half hi = __float2half_rn(x);
    __half lo = __float2half_rn(x - __half2float(hi));

    int kc = k >> 5, ks = (k >> 4) & 1, krel = k & 15;
    int mk = krel >> 3, Llo = (krel >> 1) & 3, h = krel & 1;
    int jglob = s >> 4, ms = (s >> 3) & 1, Lhi = s & 7;
    int L = Lhi * 4 + Llo, m = ms * 2 + mk;
    int inblk = L * 16 + m * 4 + h * 2;
    int blkH = ((kc * 2 + 0) * 2 + ks) * 32 + jglob;
    int blkL = ((kc * 2 + 1) * 2 + ks) * 32 + jglob;
    *(__half*)(gUimgB + blkH * 512 + inblk) = hi;
    *(__half*)(gUimgB + blkL * 512 + inblk) = lo;

    float v = x * x;
    #pragma unroll
    for (int o = 16; o > 0; o >>= 1) v += __shfl_xor_sync(0xffffffffu, v, o);
    __shared__ float ps[4];
    if (lane == 0) ps[k >> 5] = v;
    __syncthreads();
    if (k == 0) g_m2[s] = ps[0] + ps[1] + ps[2] + ps[3];
}

__global__ __launch_bounds__(256, 2)
void mb_kernel(const float* __restrict__ H, float* __restrict__ out) {
    extern __shared__ __align__(128) unsigned char smem[];
    const uint32_t sb = smem_u32(smem);
    const int tid = threadIdx.x, w = tid >> 5, lane = tid & 31;
    const int r = lane >> 2, q = lane & 3;
    const int b = blockIdx.y, tb = blockIdx.x * 32;

    // m2 -> smem
    ((float*)(smem + SM_M2))[tid]       = g_m2[tid];
    ((float*)(smem + SM_M2))[tid + 256] = g_m2[tid + 256];

    // ---- H tile (128 k x 32 t fp32) -> split f16 hi/lo -> A smem [comp][k][40h] ----
    const float* Hb = H + (size_t)b * DIM * TLEN;
    #pragma unroll
    for (int i = 0; i < 4; ++i) {
        int f4 = i * 256 + tid;          // 0..1023
        int k = f4 >> 3, t0 = (f4 & 7) * 4;
        float4 v = *reinterpret_cast<const float4*>(&Hb[(size_t)k * TLEN + tb + t0]);
        float xs[4] = {v.x, v.y, v.z, v.w};
        uint32_t hiw[2], low[2];
        #pragma unroll
        for (int j = 0; j < 2; ++j) {
            __half h0 = __float2half_rn(xs[2*j]);
            __half h1 = __float2half_rn(xs[2*j+1]);
            __half l0 = __float2half_rn(xs[2*j]   - __half2float(h0));
            __half l1 = __float2half_rn(xs[2*j+1] - __half2float(h1));
            hiw[j] = (uint32_t)__half_as_ushort(h0) | ((uint32_t)__half_as_ushort(h1) << 16);
            low[j] = (uint32_t)__half_as_ushort(l0) | ((uint32_t)__half_as_ushort(l1) << 16);
        }
        *reinterpret_cast<uint2*>(smem + SM_A +         k * 80 + t0 * 2) = make_uint2(hiw[0], hiw[1]);
        *reinterpret_cast<uint2*>(smem + SM_A + 10240 + k * 80 + t0 * 2) = make_uint2(low[0], low[1]);
    }
    __syncthreads();   // A visible

    // ---- MMA main loop: warp tile = 32 t x 64 s; B frags via direct L2 LDG.128 ----
    float acc[2][8][4];
    #pragma unroll
    for (int mi = 0; mi < 2; ++mi)
        #pragma unroll
        for (int ni = 0; ni < 8; ++ni)
            #pragma unroll
            for (int c = 0; c < 4; ++c) acc[mi][ni][c] = 0.f;

    const int lr = lane & 7;
    const uint32_t kAdd = (lane & 16) ? 8u : 0u;
    const uint32_t g1   = (lane & 8)  ? 8u : 0u;
    const uint4* imgU4 = reinterpret_cast<const uint4*>(gUimgB);

    #pragma unroll 1
    for (int kc = 0; kc < 4; ++kc) {
        #pragma unroll
        for (int ks = 0; ks < 2; ++ks) {
            const int k0g = kc * 32 + ks * 16;
            const int blkH = ((kc * 2 + 0) * 2 + ks) * 32 + 4 * w;
            const int blkL = ((kc * 2 + 1) * 2 + ks) * 32 + 4 * w;

            uint4 bh[4], bl[4];
            #pragma unroll
            for (int j = 0; j < 4; ++j) bh[j] = __ldg(&imgU4[(size_t)(blkH + j) * 32 + lane]);
            #pragma unroll
            for (int j = 0; j < 4; ++j) bl[j] = __ldg(&imgU4[(size_t)(blkL + j) * 32 + lane]);

            uint32_t afh[2][4], afl[2][4];
            #pragma unroll
            for (int mi = 0; mi < 2; ++mi)
                ldsm4t(afh[mi], sb + SM_A + (k0g + lr + kAdd) * 80 + (16*mi + g1) * 2);
            #pragma unroll
            for (int mi = 0; mi < 2; ++mi)
                ldsm4t(afl[mi], sb + SM_A + 10240 + (k0g + lr + kAdd) * 80 + (16*mi + g1) * 2);

            // p0: Ah x Bh
            #pragma unroll
            for (int mi = 0; mi < 2; ++mi)
                #pragma unroll
                for (int j = 0; j < 4; ++j) {
                    const uint32_t* bp = reinterpret_cast<const uint32_t*>(&bh[j]);
                    mma16816(acc[mi][2*j],     afh[mi], bp);
                    mma16816(acc[mi][2*j + 1], afh[mi], bp + 2);
                }
            // p1: Ah x Bl
            #pragma unroll
            for (int mi = 0; mi < 2; ++mi)
                #pragma unroll
                for (int j = 0; j < 4; ++j) {
                    const uint32_t* bp = reinterpret_cast<const uint32_t*>(&bl[j]);
                    mma16816(acc[mi][2*j],     afh[mi], bp);
                    mma16816(acc[mi][2*j + 1], afh[mi], bp + 2);
                }
            // p2: Al x Bh
            #pragma unroll
            for (int mi = 0; mi < 2; ++mi)
                #pragma unroll
                for (int j = 0; j < 4; ++j) {
                    const uint32_t* bp = reinterpret_cast<const uint32_t*>(&bh[j]);
                    mma16816(acc[mi][2*j],     afl[mi], bp);
                    mma16816(acc[mi][2*j + 1], afl[mi], bp + 2);
                }
        }
    }

    // ---- epilogue: exp (no max-sub; |logit| bounded) -> sum over s -> scale -> direct STG ----
    const float* m2s = (const float*)(smem + SM_M2);
    float* psum = (float*)(smem + SM_PSUM);
    float* cinv = (float*)(smem + SM_CINV);

    float m2v[8][2];
    #pragma unroll
    for (int ni = 0; ni < 8; ++ni) {
        m2v[ni][0] = m2s[64*w + 8*ni + 2*q];
        m2v[ni][1] = m2s[64*w + 8*ni + 2*q + 1];
    }

    #pragma unroll
    for (int mi = 0; mi < 2; ++mi)
        #pragma unroll
        for (int h = 0; h < 2; ++h) {
            float s = 0.f;
            #pragma unroll
            for (int ni = 0; ni < 8; ++ni) {
                float e0 = __expf(fmaf(2.f, acc[mi][ni][2*h],     -m2v[ni][0]));
                float e1 = __expf(fmaf(2.f, acc[mi][ni][2*h + 1], -m2v[ni][1]));
                acc[mi][ni][2*h] = e0; acc[mi][ni][2*h + 1] = e1;
                s += e0 + e1;
            }
            s += __shfl_xor_sync(0xffffffffu, s, 1);
            s += __shfl_xor_sync(0xffffffffu, s, 2);
            if (q == 0) psum[w * 32 + 16*mi + r + 8*h] = s;
        }
    __syncthreads();
    if (tid < 32) {
        float s = psum[tid];
        #pragma unroll
        for (int g = 1; g < 8; ++g) s += psum[g * 32 + tid];
        cinv[tid] = 1.f / s;
    }
    __syncthreads();

    float rinv[2][2];
    #pragma unroll
    for (int mi = 0; mi < 2; ++mi)
        #pragma unroll
        for (int h = 0; h < 2; ++h) rinv[mi][h] = cinv[16*mi + r + 8*h];

    // direct store: lanes r give 8 consecutive t -> full 32B sectors
    float* outb = out + (size_t)b * SZ * TLEN + tb;
    #pragma unroll
    for (int mi = 0; mi < 2; ++mi)
        #pragma unroll
        for (int ni = 0; ni < 8; ++ni)
            #pragma unroll
            for (int c = 0; c < 4; ++c) {
                int s = 64*w + 8*ni + 2*q + (c & 1);
                int t = 16*mi + r + 8*(c >> 1);
                outb[(size_t)s * TLEN + t] = acc[mi][ni][c] * rinv[mi][c >> 1];
            }
}

extern "C" void kernel_launch(void* const* d_in, const int* in_sizes, int n_in,
                              void* d_out, int out_size) {
    const float* H     = (const float*)d_in[0];
    const float* units = (const float*)d_in[1];
    float* out = (float*)d_out;

    cudaFuncSetAttribute(mb_kernel, cudaFuncAttributeMaxDynamicSharedMemorySize, SM_TOTAL);

    prep_kernel<<<512, 128>>>(units);
    dim3 grid(TLEN / 32, BATCH);
    mb_kernel<<<grid, 256, SM_TOTAL>>>(H, out);
}

// round 14
// speedup vs baseline: 1.0122x; 1.0122x over previous
#include <cuda_runtime.h>
#include <cuda_fp16.h>
#include <cstdint>

#define BATCH 32
#define DIM   128
#define TLEN  4096
#define SZ    512

// ---- smem byte map (per CTA, 89.3 KB -> 2 CTAs/SM) ----
#define SM_M2    0        // 512 floats  -> 2048
#define SM_PSUM  2048     // 8*32 floats -> 3072
#define SM_CINV  3072     // 32 floats   -> 3200
#define SM_A     3328     // [2 comp][128 k][40 halfs=80B]; hi @0, lo @+10240 -> 20480 B
#define SM_BP    23808    // 8 warps x (2 buf x 4096 B)  -> 65536 B
#define SM_TOTAL 89344

// fragment-packed B image, L2-resident (256 KB):
// block index = ((kc*2 + comp)*2 + ks)*32 + jglob   (jglob = s>>4), block = 512 B
// lane L, reg m (0..3), half h: element (s = 16*jglob + 8*(m>>1) + (L>>2),
//                                k = kc*32 + ks*16 + 8*(m&1) + 2*(L&3) + h)
// byte offset in block = L*16 + m*4 + h*2
__device__ __align__(128) unsigned char gUimgB[262144];
__device__ float g_m2[SZ];

__device__ __forceinline__ uint32_t smem_u32(const void* p) {
    uint32_t a;
    asm("{ .reg .u64 t; cvta.to.shared.u64 t, %1; cvt.u32.u64 %0, t; }" : "=r"(a) : "l"(p));
    return a;
}
__device__ __forceinline__ void cp_async16(uint32_t dst, const void* src) {
    asm volatile("cp.async.cg.shared.global [%0], [%1], 16;" :: "r"(dst), "l"(src) : "memory");
}
#define CP_COMMIT() asm volatile("cp.async.commit_group;" ::: "memory")
#define CP_WAIT1()  asm volatile("cp.async.wait_group 1;" ::: "memory")
#define CP_WAIT0()  asm volatile("cp.async.wait_group 0;" ::: "memory")
__device__ __forceinline__ void lds128(uint32_t* r, uint32_t a) {
    asm volatile("ld.shared.v4.u32 {%0,%1,%2,%3}, [%4];"
                 : "=r"(r[0]),"=r"(r[1]),"=r"(r[2]),"=r"(r[3]) : "r"(a));
}
__device__ __forceinline__ void ldsm4t(uint32_t* r, uint32_t a) {
    asm volatile("ldmatrix.sync.aligned.m8n8.x4.trans.shared.b16 {%0,%1,%2,%3}, [%4];"
                 : "=r"(r[0]),"=r"(r[1]),"=r"(r[2]),"=r"(r[3]) : "r"(a));
}
__device__ __forceinline__ void mma16816(float* d, const uint32_t* a, const uint32_t* b) {
    asm volatile("mma.sync.aligned.m16n8k16.row.col.f32.f16.f16.f32 "
                 "{%0,%1,%2,%3}, {%4,%5,%6,%7}, {%8,%9}, {%0,%1,%2,%3};"
                 : "+f"(d[0]),"+f"(d[1]),"+f"(d[2]),"+f"(d[3])
                 : "r"(a[0]),"r"(a[1]),"r"(a[2]),"r"(a[3]), "r"(b[0]),"r"(b[1]));
}

// ---- merged prep: fragment-packed hi/lo image + m2; 512 blocks (one s) x 128 thr (one k) ----
__global__ void prep_kernel(const float* __restrict__ units) {
    const int s = blockIdx.x, k = threadIdx.x;
    const int lane = k & 31;
    float x = units[k * SZ + s];
    __half hi = __float2half_rn(x);
    __half lo = __float2half_rn(x - __half2float(hi));

    int kc = k >> 5, ks = (k >> 4) & 1, krel = k & 15;
    int mk = krel >> 3, Llo = (krel >> 1) & 3, h = krel & 1;
    int jglob = s >> 4, ms = (s >> 3) & 1, Lhi = s & 7;
    int L = Lhi * 4 + Llo, m = ms * 2 + mk;
    int inblk = L * 16 + m * 4 + h * 2;
    int blkH = ((kc * 2 + 0) * 2 + ks) * 32 + jglob;
    int blkL = ((kc * 2 + 1) * 2 + ks) * 32 + jglob;
    *(__half*)(gUimgB + blkH * 512 + inblk) = hi;
    *(__half*)(gUimgB + blkL * 512 + inblk) = lo;

    float v = x * x;
    #pragma unroll
    for (int o = 16; o > 0; o >>= 1) v += __shfl_xor_sync(0xffffffffu, v, o);
    __shared__ float ps[4];
    if (lane == 0) ps[k >> 5] = v;
    __syncthreads();
    if (k == 0) g_m2[s] = ps[0] + ps[1] + ps[2] + ps[3];
}

// issue one chunk's B (hi+lo, 4 KB/warp) as one cp.async group
__device__ __forceinline__ void issue_chunk(int c, int w, int lane, uint32_t sb) {
    const int kc = c >> 1, ks = c & 1;
    const unsigned char* srcH = gUimgB + (size_t)(((4*kc + ks)     * 32) + 4*w) * 512 + lane * 16;
    const unsigned char* srcL = gUimgB + (size_t)(((4*kc + 2 + ks) * 32) + 4*w) * 512 + lane * 16;
    uint32_t dst = sb + SM_BP + w * 8192 + (c & 1) * 4096 + lane * 16;
    #pragma unroll
    for (int j = 0; j < 4; ++j) cp_async16(dst + j * 512,        srcH + j * 512);
    #pragma unroll
    for (int j = 0; j < 4; ++j) cp_async16(dst + 2048 + j * 512, srcL + j * 512);
    CP_COMMIT();
}

__global__ __launch_bounds__(256, 2)
void mb_kernel(const float* __restrict__ H, float* __restrict__ out) {
    extern __shared__ __align__(128) unsigned char smem[];
    const uint32_t sb = smem_u32(smem);
    const int tid = threadIdx.x, w = tid >> 5, lane = tid & 31;
    const int r = lane >> 2, q = lane & 3;
    const int b = blockIdx.y, tb = blockIdx.x * 32;

    // kick off B pipeline immediately (overlaps H prologue)
    issue_chunk(0, w, lane, sb);
    issue_chunk(1, w, lane, sb);

    // m2 -> smem
    ((float*)(smem + SM_M2))[tid]       = g_m2[tid];
    ((float*)(smem + SM_M2))[tid + 256] = g_m2[tid + 256];

    // ---- H tile (128 k x 32 t fp32) -> split f16 hi/lo -> A smem [comp][k][40h] ----
    const float* Hb = H + (size_t)b * DIM * TLEN;
    #pragma unroll
    for (int i = 0; i < 4; ++i) {
        int f4 = i * 256 + tid;          // 0..1023
        int k = f4 >> 3, t0 = (f4 & 7) * 4;
        float4 v = *reinterpret_cast<const float4*>(&Hb[(size_t)k * TLEN + tb + t0]);
        float xs[4] = {v.x, v.y, v.z, v.w};
        uint32_t hiw[2], low[2];
        #pragma unroll
        for (int j = 0; j < 2; ++j) {
            __half h0 = __float2half_rn(xs[2*j]);
            __half h1 = __float2half_rn(xs[2*j+1]);
            __half l0 = __float2half_rn(xs[2*j]   - __half2float(h0));
            __half l1 = __float2half_rn(xs[2*j+1] - __half2float(h1));
            hiw[j] = (uint32_t)__half_as_ushort(h0) | ((uint32_t)__half_as_ushort(h1) << 16);
            low[j] = (uint32_t)__half_as_ushort(l0) | ((uint32_t)__half_as_ushort(l1) << 16);
        }
        *reinterpret_cast<uint2*>(smem + SM_A +         k * 80 + t0 * 2) = make_uint2(hiw[0], hiw[1]);
        *reinterpret_cast<uint2*>(smem + SM_A + 10240 + k * 80 + t0 * 2) = make_uint2(low[0], low[1]);
    }
    __syncthreads();   // A visible

    // ---- MMA main loop: warp tile = 32 t x 64 s; barrier-free, depth-2 cp.async pipeline ----
    float acc[2][8][4];
    #pragma unroll
    for (int mi = 0; mi < 2; ++mi)
        #pragma unroll
        for (int ni = 0; ni < 8; ++ni)
            #pragma unroll
            for (int c = 0; c < 4; ++c) acc[mi][ni][c] = 0.f;

    const int lr = lane & 7;
    const uint32_t kAdd = (lane & 16) ? 8u : 0u;
    const uint32_t g1   = (lane & 8)  ? 8u : 0u;

    #pragma unroll 1
    for (int c = 0; c < 8; ++c) {
        if (c < 7) { CP_WAIT1(); } else { CP_WAIT0(); }

        const uint32_t bbase = sb + SM_BP + w * 8192 + (c & 1) * 4096 + lane * 16;
        uint32_t bh[4][4], bl[4][4];
        #pragma unroll
        for (int j = 0; j < 4; ++j) lds128(bh[j], bbase + j * 512);
        #pragma unroll
        for (int j = 0; j < 4; ++j) lds128(bl[j], bbase + 2048 + j * 512);

        const int k0g = (c >> 1) * 32 + (c & 1) * 16;
        uint32_t afh[2][4], afl[2][4];
        #pragma unroll
        for (int mi = 0; mi < 2; ++mi)
            ldsm4t(afh[mi], sb + SM_A + (k0g + lr + kAdd) * 80 + (16*mi + g1) * 2);
        #pragma unroll
        for (int mi = 0; mi < 2; ++mi)
            ldsm4t(afl[mi], sb + SM_A + 10240 + (k0g + lr + kAdd) * 80 + (16*mi + g1) * 2);

        // p0: Ah x Bh
        #pragma unroll
        for (int mi = 0; mi < 2; ++mi)
            #pragma unroll
            for (int j = 0; j < 4; ++j) {
                mma16816(acc[mi][2*j],     afh[mi], &bh[j][0]);
                mma16816(acc[mi][2*j + 1], afh[mi], &bh[j][2]);
            }
        // p1: Ah x Bl
        #pragma unroll
        for (int mi = 0; mi < 2; ++mi)
            #pragma unroll
            for (int j = 0; j < 4; ++j) {
                mma16816(acc[mi][2*j],     afh[mi], &bl[j][0]);
                mma16816(acc[mi][2*j + 1], afh[mi], &bl[j][2]);
            }
        // p2: Al x Bh
        #pragma unroll
        for (int mi = 0; mi < 2; ++mi)
            #pragma unroll
            for (int j = 0; j < 4; ++j) {
                mma16816(acc[mi][2*j],     afl[mi], &bh[j][0]);
                mma16816(acc[mi][2*j + 1], afl[mi], &bh[j][2]);
            }

        if (c < 6) issue_chunk(c + 2, w, lane, sb);
    }

    // ---- epilogue: exp (no max-sub; |logit| bounded) -> sum over s -> scale -> direct STG ----
    const float* m2s = (const float*)(smem + SM_M2);
    float* psum = (float*)(smem + SM_PSUM);
    float* cinv = (float*)(smem + SM_CINV);

    float m2v[8][2];
    #pragma unroll
    for (int ni = 0; ni < 8; ++ni) {
        m2v[ni][0] = m2s[64*w + 8*ni + 2*q];
        m2v[ni][1] = m2s[64*w + 8*ni + 2*q + 1];
    }

    #pragma unroll
    for (int mi = 0; mi < 2; ++mi)
        #pragma unroll
        for (int h = 0; h < 2; ++h) {
            float s = 0.f;
            #pragma unroll
            for (int ni = 0; ni < 8; ++ni) {
                float e0 = __expf(fmaf(2.f, acc[mi][ni][2*h],     -m2v[ni][0]));
                float e1 = __expf(fmaf(2.f, acc[mi][ni][2*h + 1], -m2v[ni][1]));
                acc[mi][ni][2*h] = e0; acc[mi][ni][2*h + 1] = e1;
                s += e0 + e1;
            }
            s += __shfl_xor_sync(0xffffffffu, s, 1);
            s += __shfl_xor_sync(0xffffffffu, s, 2);
            if (q == 0) psum[w * 32 + 16*mi + r + 8*h] = s;
        }
    __syncthreads();
    if (tid < 32) {
        float s = psum[tid];
        #pragma unroll
        for (int g = 1; g < 8; ++g) s += psum[g * 32 + tid];
        cinv[tid] = 1.f / s;
    }
    __syncthreads();

    float rinv[2][2];
    #pragma unroll
    for (int mi = 0; mi < 2; ++mi)
        #pragma unroll
        for (int h = 0; h < 2; ++h) rinv[mi][h] = cinv[16*mi + r + 8*h];

    // direct store: lanes r give 8 consecutive t -> full 32B sectors
    float* outb = out + (size_t)b * SZ * TLEN + tb;
    #pragma unroll
    for (int mi = 0; mi < 2; ++mi)
        #pragma unroll
        for (int ni = 0; ni < 8; ++ni)
            #pragma unroll
            for (int c = 0; c < 4; ++c) {
                int s = 64*w + 8*ni + 2*q + (c & 1);
                int t = 16*mi + r + 8*(c >> 1);
                outb[(size_t)s * TLEN + t] = acc[mi][ni][c] * rinv[mi][c >> 1];
            }
}

extern "C" void kernel_launch(void* const* d_in, const int* in_sizes, int n_in,
                              void* d_out, int out_size) {
    const float* H     = (const float*)d_in[0];
    const float* units = (const float*)d_in[1];
    float* out = (float*)d_out;

    cudaFuncSetAttribute(mb_kernel, cudaFuncAttributeMaxDynamicSharedMemorySize, SM_TOTAL);

    prep_kernel<<<512, 128>>>(units);
    dim3 grid(TLEN / 32, BATCH);
    mb_kernel<<<grid, 256, SM_TOTAL>>>(H, out);
}